// round 16
// baseline (speedup 1.0000x reference)
#include <cuda_runtime.h>
#include <cuda_fp16.h>
#include <cuda_bf16.h>

#define N_NODES 65536
#define N_EDGES 65536
#define DF      128
#define NNZ_CNT (1 << 20)
#define LDA     136   // smem row stride in halves: 272B -> conflict-free ldmatrix
#define BCAP    96    // bucket capacity (Poisson(16) tail @96: never hit)

// ---------------- scratch (device globals; no cudaMalloc allowed) ----------
__device__ int   g_cnt_n[N_NODES];
__device__ int   g_cnt_e[N_EDGES];
__device__ float g_degn[N_NODES];
__device__ float g_dinv[N_NODES];
__device__ float g_se[N_EDGES];
__device__ int   g_csr_e[N_EDGES * BCAP];   // node ids bucketed by edge
__device__ int   g_csr_n[N_NODES * BCAP];   // edge ids bucketed by node
__device__ __align__(16) __half g_y_h[N_NODES * DF];   // GEMM out (fp16)
__device__ __align__(16) __half g_ef_h[N_EDGES * DF];  // edge features (fp16)
__device__ __align__(16) __half g_h_h[N_NODES * DF];   // hidden (fp16)

// ---------------- preprocessing ---------------------------------------------
__global__ void k_zero() {
    int i = blockIdx.x * blockDim.x + threadIdx.x;
    if (i < N_NODES) { g_cnt_n[i] = 0; g_degn[i] = 0.f; }
    if (i < N_EDGES) { g_cnt_e[i] = 0; }
}

// single pass: bucket both CSRs + weighted node degree. 3 atomics/entry.
__global__ void k_build_direct(const int* __restrict__ nidx,
                               const int* __restrict__ eidx,
                               const float* __restrict__ w) {
    int i = blockIdx.x * blockDim.x + threadIdx.x;
    if (i < NNZ_CNT) {
        int n = nidx[i];
        int e = eidx[i];
        int p = atomicAdd(&g_cnt_e[e], 1);
        if (p < BCAP) g_csr_e[e * BCAP + p] = n;
        int q = atomicAdd(&g_cnt_n[n], 1);
        if (q < BCAP) g_csr_n[n * BCAP + q] = e;
        atomicAdd(&g_degn[n], w[e]);
    }
}

__global__ void k_scales(const float* __restrict__ w) {
    int i = blockIdx.x * blockDim.x + threadIdx.x;
    if (i < N_EDGES) {
        int c = g_cnt_e[i];
        g_se[i] = (c > 0) ? (w[i] / (float)c) : 0.f;
    }
    if (i < N_NODES) {
        float d = g_degn[i];
        g_dinv[i] = (d > 0.f) ? (1.f / d) : 0.f;
    }
}

// ---------------- HMMA GEMM -------------------------------------------------
__device__ __forceinline__ void ldsm_x4(unsigned& r0, unsigned& r1, unsigned& r2,
                                        unsigned& r3, unsigned addr) {
    asm volatile("ldmatrix.sync.aligned.m8n8.x4.shared.b16 {%0,%1,%2,%3}, [%4];"
                 : "=r"(r0), "=r"(r1), "=r"(r2), "=r"(r3) : "r"(addr));
}
__device__ __forceinline__ void ldsm_x4t(unsigned& r0, unsigned& r1, unsigned& r2,
                                         unsigned& r3, unsigned addr) {
    asm volatile("ldmatrix.sync.aligned.m8n8.x4.trans.shared.b16 {%0,%1,%2,%3}, [%4];"
                 : "=r"(r0), "=r"(r1), "=r"(r2), "=r"(r3) : "r"(addr));
}
#define MMA16816(c, a0, a1, a2, a3, b0, b1) \
    asm volatile("mma.sync.aligned.m16n8k16.row.col.f32.f16.f16.f32 " \
                 "{%0,%1,%2,%3}, {%4,%5,%6,%7}, {%8,%9}, {%0,%1,%2,%3};" \
                 : "+f"(c[0]), "+f"(c[1]), "+f"(c[2]), "+f"(c[3]) \
                 : "r"(a0), "r"(a1), "r"(a2), "r"(a3), "r"(b0), "r"(b1))

template<int A_FP16>
__global__ void __launch_bounds__(256) k_gemm_mma(const void* __restrict__ Aptr,
                                                  const float* __restrict__ W,
                                                  __half* __restrict__ C) {
    extern __shared__ __half smh[];
    __half* sA = smh;               // 128 x LDA
    __half* sB = smh + 128 * LDA;   // 128 x LDA (W, k-major rows)
    int tid = threadIdx.x;
    int row0 = blockIdx.x * 128;

    // ---- stage A first (DRAM, long latency), loads batched x4 ----
    if (A_FP16) {
        const uint4* A4 = (const uint4*)((const __half*)Aptr + (size_t)row0 * DF);
#pragma unroll
        for (int b = 0; b < 8; b += 4) {
            uint4 v[4];
#pragma unroll
            for (int u = 0; u < 4; u++) v[u] = A4[tid + (b + u) * 256];
#pragma unroll
            for (int u = 0; u < 4; u++) {
                int i = tid + (b + u) * 256;
                int r = i >> 4, c = (i & 15) * 8;
                *(uint4*)&sA[r * LDA + c] = v[u];
            }
        }
    } else {
        const float4* A4 = (const float4*)((const float*)Aptr + (size_t)row0 * DF);
#pragma unroll
        for (int b = 0; b < 16; b += 4) {
            float4 v[4];
#pragma unroll
            for (int u = 0; u < 4; u++) v[u] = A4[tid + (b + u) * 256];
#pragma unroll
            for (int u = 0; u < 4; u++) {
                int i = tid + (b + u) * 256;
                int r = i >> 5, c = (i & 31) * 4;
                __half2* d = (__half2*)&sA[r * LDA + c];
                d[0] = __floats2half2_rn(v[u].x, v[u].y);
                d[1] = __floats2half2_rn(v[u].z, v[u].w);
            }
        }
    }

    // ---- stage W (L2-resident), loads batched x4 ----
    const float4* W4 = (const float4*)W;
#pragma unroll
    for (int b = 0; b < 16; b += 4) {
        float4 v[4];
#pragma unroll
        for (int u = 0; u < 4; u++) v[u] = W4[tid + (b + u) * 256];
#pragma unroll
        for (int u = 0; u < 4; u++) {
            int i = tid + (b + u) * 256;
            int k = i >> 5, n = (i & 31) * 4;
            __half2* d = (__half2*)&sB[k * LDA + n];
            d[0] = __floats2half2_rn(v[u].x, v[u].y);
            d[1] = __floats2half2_rn(v[u].z, v[u].w);
        }
    }
    __syncthreads();

    int warp = tid >> 5, lane = tid & 31;
    int wrow = warp * 16;

    float acc[16][4];
#pragma unroll
    for (int t = 0; t < 16; t++)
#pragma unroll
        for (int c = 0; c < 4; c++) acc[t][c] = 0.f;

    unsigned aBase = (unsigned)__cvta_generic_to_shared(
        &sA[(wrow + (lane & 15)) * LDA + (lane >> 4) * 8]);
    int bk = (lane & 15);
    int bn = (lane >> 4) * 8;
    unsigned bBase = (unsigned)__cvta_generic_to_shared(&sB[bk * LDA + bn]);

#pragma unroll
    for (int k0 = 0; k0 < 8; k0++) {
        unsigned a0, a1, a2, a3;
        ldsm_x4(a0, a1, a2, a3, aBase + k0 * 32);
        unsigned bRow = bBase + (unsigned)(k0 * 16 * LDA * 2);
#pragma unroll
        for (int np = 0; np < 8; np++) {
            unsigned b0, b1, b2, b3;
            ldsm_x4t(b0, b1, b2, b3, bRow + np * 32);
            MMA16816(acc[2 * np],     a0, a1, a2, a3, b0, b1);
            MMA16816(acc[2 * np + 1], a0, a1, a2, a3, b2, b3);
        }
    }
    __syncthreads();  // done reading sA/sB; reuse sA as C staging

    int crow = wrow + (lane >> 2);
    int ccol = 2 * (lane & 3);
#pragma unroll
    for (int t = 0; t < 16; t++) {
        *(__half2*)&sA[crow * LDA + t * 8 + ccol]       = __floats2half2_rn(acc[t][0], acc[t][1]);
        *(__half2*)&sA[(crow + 8) * LDA + t * 8 + ccol] = __floats2half2_rn(acc[t][2], acc[t][3]);
    }
    __syncthreads();

    for (int i = tid; i < 128 * DF / 8; i += 256) {
        int r = i >> 4, c = (i & 15) * 8;
        *(uint4*)&C[(size_t)(row0 + r) * DF + c] = *(const uint4*)&sA[r * LDA + c];
    }
}

// ---------------- segment aggregation ---------------------------------------
// One warp per segment. Half-warp row split: lanes 0-15 gather even rows,
// lanes 16-31 odd rows, 16B per lane. Indices prefetched into registers,
// broadcast by shfl. Main loop: 4 rows/lane (8 rows/warp-step) combined by a
// 2-level packed fp16 HADD2 tree before a single convert + fp32 accumulate.
// shfl_xor(16) combines half-warps; lanes 0-15 write the 256B output row.
__device__ __forceinline__ void agg_add(float* acc, uint4 u) {
    float2 f0 = __half22float2(*(const __half2*)&u.x);
    float2 f1 = __half22float2(*(const __half2*)&u.y);
    float2 f2 = __half22float2(*(const __half2*)&u.z);
    float2 f3 = __half22float2(*(const __half2*)&u.w);
    acc[0] += f0.x; acc[1] += f0.y; acc[2] += f1.x; acc[3] += f1.y;
    acc[4] += f2.x; acc[5] += f2.y; acc[6] += f3.x; acc[7] += f3.y;
}

template<int OUT_HALF, int RELU, int HAS_BIAS>
__global__ void k_agg(const __half* __restrict__ src, void* __restrict__ dst,
                      const int* __restrict__ cnt, const int* __restrict__ csr,
                      const float* __restrict__ scale, const float* __restrict__ bias,
                      int nseg) {
    int gwarp = (blockIdx.x * blockDim.x + threadIdx.x) >> 5;
    int lane = threadIdx.x & 31;
    if (gwarp >= nseg) return;
    int len = cnt[gwarp];
    if (len > BCAP) len = BCAP;
    const int* idxp = csr + (size_t)gwarp * BCAP;
    const uint4* s4 = (const uint4*)src;
    int hw = lane >> 4;       // 0: even rows, 1: odd rows
    int sub = lane & 15;      // 16B chunk within row

    float acc[8];
#pragma unroll
    for (int t = 0; t < 8; t++) acc[t] = 0.f;

    for (int base = 0; base < len; base += 32) {
        int m = len - base;
        if (m > 32) m = 32;
        int myidx = (lane < m) ? idxp[base + lane] : 0;
        int j = 0;
        // 8 rows per step: each lane tree-reduces 4 rows in packed fp16
        for (; j + 7 < m; j += 8) {
            int r0 = __shfl_sync(~0u, myidx, j + hw);
            int r1 = __shfl_sync(~0u, myidx, j + 2 + hw);
            int r2 = __shfl_sync(~0u, myidx, j + 4 + hw);
            int r3 = __shfl_sync(~0u, myidx, j + 6 + hw);
            uint4 u0 = s4[(size_t)r0 * 16 + sub];
            uint4 u1 = s4[(size_t)r1 * 16 + sub];
            uint4 u2 = s4[(size_t)r2 * 16 + sub];
            uint4 u3 = s4[(size_t)r3 * 16 + sub];
            __half2 s0x = __hadd2(*(__half2*)&u0.x, *(__half2*)&u1.x);
            __half2 s0y = __hadd2(*(__half2*)&u0.y, *(__half2*)&u1.y);
            __half2 s0z = __hadd2(*(__half2*)&u0.z, *(__half2*)&u1.z);
            __half2 s0w = __hadd2(*(__half2*)&u0.w, *(__half2*)&u1.w);
            __half2 s1x = __hadd2(*(__half2*)&u2.x, *(__half2*)&u3.x);
            __half2 s1y = __hadd2(*(__half2*)&u2.y, *(__half2*)&u3.y);
            __half2 s1z = __hadd2(*(__half2*)&u2.z, *(__half2*)&u3.z);
            __half2 s1w = __hadd2(*(__half2*)&u2.w, *(__half2*)&u3.w);
            __half2 q0 = __hadd2(s0x, s1x);
            __half2 q1 = __hadd2(s0y, s1y);
            __half2 q2 = __hadd2(s0z, s1z);
            __half2 q3 = __hadd2(s0w, s1w);
            float2 f0 = __half22float2(q0);
            float2 f1 = __half22float2(q1);
            float2 f2 = __half22float2(q2);
            float2 f3 = __half22float2(q3);
            acc[0] += f0.x; acc[1] += f0.y; acc[2] += f1.x; acc[3] += f1.y;
            acc[4] += f2.x; acc[5] += f2.y; acc[6] += f3.x; acc[7] += f3.y;
        }
        // 4 rows per step: pairwise fp16 reduce
        for (; j + 3 < m; j += 4) {
            int r0 = __shfl_sync(~0u, myidx, j + hw);
            int r1 = __shfl_sync(~0u, myidx, j + 2 + hw);
            uint4 u0 = s4[(size_t)r0 * 16 + sub];
            uint4 u1 = s4[(size_t)r1 * 16 + sub];
            __half2 q0 = __hadd2(*(__half2*)&u0.x, *(__half2*)&u1.x);
            __half2 q1 = __hadd2(*(__half2*)&u0.y, *(__half2*)&u1.y);
            __half2 q2 = __hadd2(*(__half2*)&u0.z, *(__half2*)&u1.z);
            __half2 q3 = __hadd2(*(__half2*)&u0.w, *(__half2*)&u1.w);
            float2 f0 = __half22float2(q0);
            float2 f1 = __half22float2(q1);
            float2 f2 = __half22float2(q2);
            float2 f3 = __half22float2(q3);
            acc[0] += f0.x; acc[1] += f0.y; acc[2] += f1.x; acc[3] += f1.y;
            acc[4] += f2.x; acc[5] += f2.y; acc[6] += f3.x; acc[7] += f3.y;
        }
        // tail rows (exact path)
        for (; j < m; j += 2) {
            int jj = j + hw;
            int r = __shfl_sync(~0u, myidx, (jj < m) ? jj : (m - 1));
            if (jj < m) {
                uint4 u = s4[(size_t)r * 16 + sub];
                agg_add(acc, u);
            }
        }
    }

    // combine the two half-warps
#pragma unroll
    for (int t = 0; t < 8; t++) acc[t] += __shfl_xor_sync(~0u, acc[t], 16);

    if (lane < 16) {
        float sc = scale[gwarp];
        float o[8];
#pragma unroll
        for (int t = 0; t < 8; t++) o[t] = acc[t] * sc;
        if (HAS_BIAS) {
            float4 b0 = ((const float4*)bias)[sub * 2];
            float4 b1 = ((const float4*)bias)[sub * 2 + 1];
            o[0] += b0.x; o[1] += b0.y; o[2] += b0.z; o[3] += b0.w;
            o[4] += b1.x; o[5] += b1.y; o[6] += b1.z; o[7] += b1.w;
        }
        if (RELU) {
#pragma unroll
            for (int t = 0; t < 8; t++) o[t] = fmaxf(o[t], 0.f);
        }
        if (OUT_HALF) {
            __half2 h0 = __floats2half2_rn(o[0], o[1]);
            __half2 h1 = __floats2half2_rn(o[2], o[3]);
            __half2 h2 = __floats2half2_rn(o[4], o[5]);
            __half2 h3 = __floats2half2_rn(o[6], o[7]);
            uint4 st;
            st.x = *(unsigned*)&h0; st.y = *(unsigned*)&h1;
            st.z = *(unsigned*)&h2; st.w = *(unsigned*)&h3;
            ((uint4*)dst)[(size_t)gwarp * 16 + sub] = st;
        } else {
            float4* d4 = (float4*)dst;
            d4[(size_t)gwarp * 32 + sub * 2]     = make_float4(o[0], o[1], o[2], o[3]);
            d4[(size_t)gwarp * 32 + sub * 2 + 1] = make_float4(o[4], o[5], o[6], o[7]);
        }
    }
}

// ---------------- launch ---------------------------------------------------
extern "C" void kernel_launch(void* const* d_in, const int* in_sizes, int n_in,
                              void* d_out, int out_size) {
    const float* x   = (const float*)d_in[0];
    const int*   hei = (const int*)d_in[1];
    const float* w   = (const float*)d_in[2];
    const float* W1  = (const float*)d_in[3];
    const float* b1  = (const float*)d_in[4];
    const float* W2  = (const float*)d_in[5];
    const float* b2  = (const float*)d_in[6];
    float* out = (float*)d_out;

    const int* nidx = hei;
    const int* eidx = hei + NNZ_CNT;

    int *p_cnt_e, *p_cnt_n, *p_csr_e, *p_csr_n;
    float *p_se, *p_dinv;
    __half *p_y, *p_ef, *p_h;
    cudaGetSymbolAddress((void**)&p_cnt_e, g_cnt_e);
    cudaGetSymbolAddress((void**)&p_cnt_n, g_cnt_n);
    cudaGetSymbolAddress((void**)&p_csr_e, g_csr_e);
    cudaGetSymbolAddress((void**)&p_csr_n, g_csr_n);
    cudaGetSymbolAddress((void**)&p_y,    g_y_h);
    cudaGetSymbolAddress((void**)&p_ef,   g_ef_h);
    cudaGetSymbolAddress((void**)&p_h,    g_h_h);
    cudaGetSymbolAddress((void**)&p_se,   g_se);
    cudaGetSymbolAddress((void**)&p_dinv, g_dinv);

    const int GEMM_SMEM = 2 * 128 * LDA * 2;  // 69632 B
    cudaFuncSetAttribute(k_gemm_mma<0>, cudaFuncAttributeMaxDynamicSharedMemorySize, GEMM_SMEM);
    cudaFuncSetAttribute(k_gemm_mma<1>, cudaFuncAttributeMaxDynamicSharedMemorySize, GEMM_SMEM);

    // lazily-created side stream + fork/join events (host resources, no device mem)
    static cudaStream_t s_gemm = nullptr;
    static cudaEvent_t ev_fork = nullptr, ev_join = nullptr;
    if (!s_gemm) {
        cudaStreamCreateWithFlags(&s_gemm, cudaStreamNonBlocking);
        cudaEventCreateWithFlags(&ev_fork, cudaEventDisableTiming);
        cudaEventCreateWithFlags(&ev_join, cudaEventDisableTiming);
    }

    // -------- fork: GEMM1 runs concurrent with bucket build ---------------
    cudaEventRecord(ev_fork, 0);
    cudaStreamWaitEvent(s_gemm, ev_fork, 0);
    k_gemm_mma<0><<<N_NODES / 128, 256, GEMM_SMEM, s_gemm>>>(x, W1, p_y);
    cudaEventRecord(ev_join, s_gemm);

    // -------- preprocessing: direct bucket build (no hist, no scans) -------
    k_zero<<<256, 256>>>();
    k_build_direct<<<NNZ_CNT / 256, 256>>>(nidx, eidx, w);
    k_scales<<<256, 256>>>(w);

    // join before first agg (needs both y and csr)
    cudaStreamWaitEvent(0, ev_join, 0);

    const int AGG_BLOCKS = N_NODES / 8;  // 8 warps per 256-thread block

    // -------- layer 1 ------------------------------------------------------
    k_agg<1, 0, 0><<<AGG_BLOCKS, 256>>>(p_y, p_ef, p_cnt_e, p_csr_e, p_se, nullptr, N_EDGES);
    k_agg<1, 1, 1><<<AGG_BLOCKS, 256>>>(p_ef, p_h, p_cnt_n, p_csr_n, p_dinv, b1, N_NODES);

    // -------- layer 2 ------------------------------------------------------
    k_gemm_mma<1><<<N_NODES / 128, 256, GEMM_SMEM>>>(p_h, W2, p_y);
    k_agg<1, 0, 0><<<AGG_BLOCKS, 256>>>(p_y, p_ef, p_cnt_e, p_csr_e, p_se, nullptr, N_EDGES);
    k_agg<0, 0, 1><<<AGG_BLOCKS, 256>>>(p_ef, out, p_cnt_n, p_csr_n, p_dinv, b2, N_NODES);
}

// round 17
// speedup vs baseline: 1.0295x; 1.0295x over previous
#include <cuda_runtime.h>
#include <cuda_fp16.h>
#include <cuda_bf16.h>

#define N_NODES 65536
#define N_EDGES 65536
#define DF      128
#define NNZ_CNT (1 << 20)
#define LDA     136   // smem row stride in halves: 272B -> conflict-free ldmatrix
#define BCAP    96    // bucket capacity (Poisson(16) tail @96: never hit)

// ---------------- scratch (device globals; no cudaMalloc allowed) ----------
__device__ int   g_cnt_n[N_NODES];
__device__ int   g_cnt_e[N_EDGES];
__device__ float g_degn[N_NODES];
__device__ float g_dinv[N_NODES];
__device__ float g_se[N_EDGES];
__device__ int   g_csr_e[N_EDGES * BCAP];   // node ids bucketed by edge
__device__ int   g_csr_n[N_NODES * BCAP];   // edge ids bucketed by node
__device__ __align__(16) __half g_y_h[N_NODES * DF];   // GEMM out (fp16)
__device__ __align__(16) __half g_ef_h[N_EDGES * DF];  // edge features (fp16)
__device__ __align__(16) __half g_h_h[N_NODES * DF];   // hidden (fp16)

// ---------------- preprocessing ---------------------------------------------
__global__ void k_zero() {
    int i = blockIdx.x * blockDim.x + threadIdx.x;
    if (i < N_NODES) { g_cnt_n[i] = 0; g_degn[i] = 0.f; }
    if (i < N_EDGES) { g_cnt_e[i] = 0; }
}

// single pass: bucket both CSRs + weighted node degree. 3 atomics/entry.
__global__ void k_build_direct(const int* __restrict__ nidx,
                               const int* __restrict__ eidx,
                               const float* __restrict__ w) {
    int i = blockIdx.x * blockDim.x + threadIdx.x;
    if (i < NNZ_CNT) {
        int n = nidx[i];
        int e = eidx[i];
        int p = atomicAdd(&g_cnt_e[e], 1);
        if (p < BCAP) g_csr_e[e * BCAP + p] = n;
        int q = atomicAdd(&g_cnt_n[n], 1);
        if (q < BCAP) g_csr_n[n * BCAP + q] = e;
        atomicAdd(&g_degn[n], w[e]);
    }
}

// batched x4: 64 blocks x 256 threads, each thread 4 edge + 4 node entries
__global__ void __launch_bounds__(256) k_scales(const float* __restrict__ w) {
    int t = blockIdx.x * blockDim.x + threadIdx.x;   // 0..16383
    int base = t * 4;
    int   ce[4];  float we[4];
    float dn[4];
#pragma unroll
    for (int u = 0; u < 4; u++) ce[u] = g_cnt_e[base + u];
#pragma unroll
    for (int u = 0; u < 4; u++) we[u] = w[base + u];
#pragma unroll
    for (int u = 0; u < 4; u++) dn[u] = g_degn[base + u];
#pragma unroll
    for (int u = 0; u < 4; u++)
        g_se[base + u] = (ce[u] > 0) ? (we[u] / (float)ce[u]) : 0.f;
#pragma unroll
    for (int u = 0; u < 4; u++)
        g_dinv[base + u] = (dn[u] > 0.f) ? (1.f / dn[u]) : 0.f;
}

// ---------------- HMMA GEMM -------------------------------------------------
__device__ __forceinline__ void ldsm_x4(unsigned& r0, unsigned& r1, unsigned& r2,
                                        unsigned& r3, unsigned addr) {
    asm volatile("ldmatrix.sync.aligned.m8n8.x4.shared.b16 {%0,%1,%2,%3}, [%4];"
                 : "=r"(r0), "=r"(r1), "=r"(r2), "=r"(r3) : "r"(addr));
}
__device__ __forceinline__ void ldsm_x4t(unsigned& r0, unsigned& r1, unsigned& r2,
                                         unsigned& r3, unsigned addr) {
    asm volatile("ldmatrix.sync.aligned.m8n8.x4.trans.shared.b16 {%0,%1,%2,%3}, [%4];"
                 : "=r"(r0), "=r"(r1), "=r"(r2), "=r"(r3) : "r"(addr));
}
#define MMA16816(c, a0, a1, a2, a3, b0, b1) \
    asm volatile("mma.sync.aligned.m16n8k16.row.col.f32.f16.f16.f32 " \
                 "{%0,%1,%2,%3}, {%4,%5,%6,%7}, {%8,%9}, {%0,%1,%2,%3};" \
                 : "+f"(c[0]), "+f"(c[1]), "+f"(c[2]), "+f"(c[3]) \
                 : "r"(a0), "r"(a1), "r"(a2), "r"(a3), "r"(b0), "r"(b1))

template<int A_FP16>
__global__ void __launch_bounds__(256) k_gemm_mma(const void* __restrict__ Aptr,
                                                  const float* __restrict__ W,
                                                  __half* __restrict__ C,
                                                  int bid0) {
    extern __shared__ __half smh[];
    __half* sA = smh;               // 128 x LDA
    __half* sB = smh + 128 * LDA;   // 128 x LDA (W, k-major rows)
    int tid = threadIdx.x;
    int row0 = (blockIdx.x + bid0) * 128;

    // ---- stage A first (DRAM/L2, long latency), loads batched x4 ----
    if (A_FP16) {
        const uint4* A4 = (const uint4*)((const __half*)Aptr + (size_t)row0 * DF);
#pragma unroll
        for (int b = 0; b < 8; b += 4) {
            uint4 v[4];
#pragma unroll
            for (int u = 0; u < 4; u++) v[u] = A4[tid + (b + u) * 256];
#pragma unroll
            for (int u = 0; u < 4; u++) {
                int i = tid + (b + u) * 256;
                int r = i >> 4, c = (i & 15) * 8;
                *(uint4*)&sA[r * LDA + c] = v[u];
            }
        }
    } else {
        const float4* A4 = (const float4*)((const float*)Aptr + (size_t)row0 * DF);
#pragma unroll
        for (int b = 0; b < 16; b += 4) {
            float4 v[4];
#pragma unroll
            for (int u = 0; u < 4; u++) v[u] = A4[tid + (b + u) * 256];
#pragma unroll
            for (int u = 0; u < 4; u++) {
                int i = tid + (b + u) * 256;
                int r = i >> 5, c = (i & 31) * 4;
                __half2* d = (__half2*)&sA[r * LDA + c];
                d[0] = __floats2half2_rn(v[u].x, v[u].y);
                d[1] = __floats2half2_rn(v[u].z, v[u].w);
            }
        }
    }

    // ---- stage W (L2-resident), loads batched x4 ----
    const float4* W4 = (const float4*)W;
#pragma unroll
    for (int b = 0; b < 16; b += 4) {
        float4 v[4];
#pragma unroll
        for (int u = 0; u < 4; u++) v[u] = W4[tid + (b + u) * 256];
#pragma unroll
        for (int u = 0; u < 4; u++) {
            int i = tid + (b + u) * 256;
            int k = i >> 5, n = (i & 31) * 4;
            __half2* d = (__half2*)&sB[k * LDA + n];
            d[0] = __floats2half2_rn(v[u].x, v[u].y);
            d[1] = __floats2half2_rn(v[u].z, v[u].w);
        }
    }
    __syncthreads();

    int warp = tid >> 5, lane = tid & 31;
    int wrow = warp * 16;

    float acc[16][4];
#pragma unroll
    for (int t = 0; t < 16; t++)
#pragma unroll
        for (int c = 0; c < 4; c++) acc[t][c] = 0.f;

    unsigned aBase = (unsigned)__cvta_generic_to_shared(
        &sA[(wrow + (lane & 15)) * LDA + (lane >> 4) * 8]);
    int bk = (lane & 15);
    int bn = (lane >> 4) * 8;
    unsigned bBase = (unsigned)__cvta_generic_to_shared(&sB[bk * LDA + bn]);

#pragma unroll
    for (int k0 = 0; k0 < 8; k0++) {
        unsigned a0, a1, a2, a3;
        ldsm_x4(a0, a1, a2, a3, aBase + k0 * 32);
        unsigned bRow = bBase + (unsigned)(k0 * 16 * LDA * 2);
#pragma unroll
        for (int np = 0; np < 8; np++) {
            unsigned b0, b1, b2, b3;
            ldsm_x4t(b0, b1, b2, b3, bRow + np * 32);
            MMA16816(acc[2 * np],     a0, a1, a2, a3, b0, b1);
            MMA16816(acc[2 * np + 1], a0, a1, a2, a3, b2, b3);
        }
    }
    __syncthreads();  // done reading sA/sB; reuse sA as C staging

    int crow = wrow + (lane >> 2);
    int ccol = 2 * (lane & 3);
#pragma unroll
    for (int t = 0; t < 16; t++) {
        *(__half2*)&sA[crow * LDA + t * 8 + ccol]       = __floats2half2_rn(acc[t][0], acc[t][1]);
        *(__half2*)&sA[(crow + 8) * LDA + t * 8 + ccol] = __floats2half2_rn(acc[t][2], acc[t][3]);
    }
    __syncthreads();

    for (int i = tid; i < 128 * DF / 8; i += 256) {
        int r = i >> 4, c = (i & 15) * 8;
        *(uint4*)&C[(size_t)(row0 + r) * DF + c] = *(const uint4*)&sA[r * LDA + c];
    }
}

// ---------------- segment aggregation ---------------------------------------
// One warp per segment (seg = seg0 + warpid). Half-warp row split; indices
// prefetched+shfl-broadcast; pairwise packed-fp16 HADD2 pre-reduction.
__device__ __forceinline__ void agg_add(float* acc, uint4 u) {
    float2 f0 = __half22float2(*(const __half2*)&u.x);
    float2 f1 = __half22float2(*(const __half2*)&u.y);
    float2 f2 = __half22float2(*(const __half2*)&u.z);
    float2 f3 = __half22float2(*(const __half2*)&u.w);
    acc[0] += f0.x; acc[1] += f0.y; acc[2] += f1.x; acc[3] += f1.y;
    acc[4] += f2.x; acc[5] += f2.y; acc[6] += f3.x; acc[7] += f3.y;
}

template<int OUT_HALF, int RELU, int HAS_BIAS>
__global__ void k_agg(const __half* __restrict__ src, void* __restrict__ dst,
                      const int* __restrict__ cnt, const int* __restrict__ csr,
                      const float* __restrict__ scale, const float* __restrict__ bias,
                      int seg0, int nseg) {
    int wid = (blockIdx.x * blockDim.x + threadIdx.x) >> 5;
    int lane = threadIdx.x & 31;
    if (wid >= nseg) return;
    int gwarp = seg0 + wid;
    int len = cnt[gwarp];
    if (len > BCAP) len = BCAP;
    const int* idxp = csr + (size_t)gwarp * BCAP;
    const uint4* s4 = (const uint4*)src;
    int hw = lane >> 4;       // 0: even rows, 1: odd rows
    int sub = lane & 15;      // 16B chunk within row

    float acc[8];
#pragma unroll
    for (int t = 0; t < 8; t++) acc[t] = 0.f;

    for (int base = 0; base < len; base += 32) {
        int m = len - base;
        if (m > 32) m = 32;
        int myidx = (lane < m) ? idxp[base + lane] : 0;
        int j = 0;
        for (; j + 3 < m; j += 4) {
            int r0 = __shfl_sync(~0u, myidx, j + hw);
            int r1 = __shfl_sync(~0u, myidx, j + 2 + hw);
            uint4 u0 = s4[(size_t)r0 * 16 + sub];
            uint4 u1 = s4[(size_t)r1 * 16 + sub];
            __half2 q0 = __hadd2(*(__half2*)&u0.x, *(__half2*)&u1.x);
            __half2 q1 = __hadd2(*(__half2*)&u0.y, *(__half2*)&u1.y);
            __half2 q2 = __hadd2(*(__half2*)&u0.z, *(__half2*)&u1.z);
            __half2 q3 = __hadd2(*(__half2*)&u0.w, *(__half2*)&u1.w);
            float2 f0 = __half22float2(q0);
            float2 f1 = __half22float2(q1);
            float2 f2 = __half22float2(q2);
            float2 f3 = __half22float2(q3);
            acc[0] += f0.x; acc[1] += f0.y; acc[2] += f1.x; acc[3] += f1.y;
            acc[4] += f2.x; acc[5] += f2.y; acc[6] += f3.x; acc[7] += f3.y;
        }
        for (; j < m; j += 2) {
            int jj = j + hw;
            int r = __shfl_sync(~0u, myidx, (jj < m) ? jj : (m - 1));
            if (jj < m) {
                uint4 u = s4[(size_t)r * 16 + sub];
                agg_add(acc, u);
            }
        }
    }

    // combine the two half-warps
#pragma unroll
    for (int t = 0; t < 8; t++) acc[t] += __shfl_xor_sync(~0u, acc[t], 16);

    if (lane < 16) {
        float sc = scale[gwarp];
        float o[8];
#pragma unroll
        for (int t = 0; t < 8; t++) o[t] = acc[t] * sc;
        if (HAS_BIAS) {
            float4 b0 = ((const float4*)bias)[sub * 2];
            float4 b1 = ((const float4*)bias)[sub * 2 + 1];
            o[0] += b0.x; o[1] += b0.y; o[2] += b0.z; o[3] += b0.w;
            o[4] += b1.x; o[5] += b1.y; o[6] += b1.z; o[7] += b1.w;
        }
        if (RELU) {
#pragma unroll
            for (int t = 0; t < 8; t++) o[t] = fmaxf(o[t], 0.f);
        }
        if (OUT_HALF) {
            __half2 h0 = __floats2half2_rn(o[0], o[1]);
            __half2 h1 = __floats2half2_rn(o[2], o[3]);
            __half2 h2 = __floats2half2_rn(o[4], o[5]);
            __half2 h3 = __floats2half2_rn(o[6], o[7]);
            uint4 st;
            st.x = *(unsigned*)&h0; st.y = *(unsigned*)&h1;
            st.z = *(unsigned*)&h2; st.w = *(unsigned*)&h3;
            ((uint4*)dst)[(size_t)gwarp * 16 + sub] = st;
        } else {
            float4* d4 = (float4*)dst;
            d4[(size_t)gwarp * 32 + sub * 2]     = make_float4(o[0], o[1], o[2], o[3]);
            d4[(size_t)gwarp * 32 + sub * 2 + 1] = make_float4(o[4], o[5], o[6], o[7]);
        }
    }
}

// ---------------- launch ---------------------------------------------------
extern "C" void kernel_launch(void* const* d_in, const int* in_sizes, int n_in,
                              void* d_out, int out_size) {
    const float* x   = (const float*)d_in[0];
    const int*   hei = (const int*)d_in[1];
    const float* w   = (const float*)d_in[2];
    const float* W1  = (const float*)d_in[3];
    const float* b1  = (const float*)d_in[4];
    const float* W2  = (const float*)d_in[5];
    const float* b2  = (const float*)d_in[6];
    float* out = (float*)d_out;

    const int* nidx = hei;
    const int* eidx = hei + NNZ_CNT;

    int *p_cnt_e, *p_cnt_n, *p_csr_e, *p_csr_n;
    float *p_se, *p_dinv;
    __half *p_y, *p_ef, *p_h;
    cudaGetSymbolAddress((void**)&p_cnt_e, g_cnt_e);
    cudaGetSymbolAddress((void**)&p_cnt_n, g_cnt_n);
    cudaGetSymbolAddress((void**)&p_csr_e, g_csr_e);
    cudaGetSymbolAddress((void**)&p_csr_n, g_csr_n);
    cudaGetSymbolAddress((void**)&p_y,    g_y_h);
    cudaGetSymbolAddress((void**)&p_ef,   g_ef_h);
    cudaGetSymbolAddress((void**)&p_h,    g_h_h);
    cudaGetSymbolAddress((void**)&p_se,   g_se);
    cudaGetSymbolAddress((void**)&p_dinv, g_dinv);

    const int GEMM_SMEM = 2 * 128 * LDA * 2;  // 69632 B
    cudaFuncSetAttribute(k_gemm_mma<0>, cudaFuncAttributeMaxDynamicSharedMemorySize, GEMM_SMEM);
    cudaFuncSetAttribute(k_gemm_mma<1>, cudaFuncAttributeMaxDynamicSharedMemorySize, GEMM_SMEM);

    // lazily-created side stream + fork/join events (host resources, no device mem)
    static cudaStream_t s_side = nullptr;
    static cudaEvent_t ev_fork = nullptr, ev_join = nullptr, ev_n0 = nullptr, ev_g0 = nullptr;
    if (!s_side) {
        cudaStreamCreateWithFlags(&s_side, cudaStreamNonBlocking);
        cudaEventCreateWithFlags(&ev_fork, cudaEventDisableTiming);
        cudaEventCreateWithFlags(&ev_join, cudaEventDisableTiming);
        cudaEventCreateWithFlags(&ev_n0, cudaEventDisableTiming);
        cudaEventCreateWithFlags(&ev_g0, cudaEventDisableTiming);
    }

    // -------- fork: GEMM1 runs concurrent with bucket build ---------------
    cudaEventRecord(ev_fork, 0);
    cudaStreamWaitEvent(s_side, ev_fork, 0);
    k_gemm_mma<0><<<N_NODES / 128, 256, GEMM_SMEM, s_side>>>(x, W1, p_y, 0);
    cudaEventRecord(ev_join, s_side);

    // -------- preprocessing: direct bucket build (no hist, no scans) -------
    k_zero<<<256, 256>>>();
    k_build_direct<<<NNZ_CNT / 256, 256>>>(nidx, eidx, w);
    k_scales<<<64, 256>>>(w);

    // join before first agg (needs both y and csr)
    cudaStreamWaitEvent(0, ev_join, 0);

    const int AGG_BLOCKS = N_NODES / 8;   // 8 warps per 256-thread block
    const int HALF_SEGS  = N_NODES / 2;
    const int HALF_BLOCKS = AGG_BLOCKS / 2;

    // -------- layer 1 ------------------------------------------------------
    k_agg<1, 0, 0><<<AGG_BLOCKS, 256>>>(p_y, p_ef, p_cnt_e, p_csr_e, p_se, nullptr,
                                        0, N_EDGES);
    // node agg split in halves; GEMM2(h0) pipelines against agg_n1(h1)
    k_agg<1, 1, 1><<<HALF_BLOCKS, 256>>>(p_ef, p_h, p_cnt_n, p_csr_n, p_dinv, b1,
                                         0, HALF_SEGS);
    cudaEventRecord(ev_n0, 0);
    cudaStreamWaitEvent(s_side, ev_n0, 0);
    k_gemm_mma<1><<<N_NODES / 256, 256, GEMM_SMEM, s_side>>>(p_h, W2, p_y, 0);
    cudaEventRecord(ev_g0, s_side);

    k_agg<1, 1, 1><<<HALF_BLOCKS, 256>>>(p_ef, p_h, p_cnt_n, p_csr_n, p_dinv, b1,
                                         HALF_SEGS, HALF_SEGS);
    // -------- layer 2 ------------------------------------------------------
    k_gemm_mma<1><<<N_NODES / 256, 256, GEMM_SMEM>>>(p_h, W2, p_y, N_NODES / 256);
    cudaStreamWaitEvent(0, ev_g0, 0);

    k_agg<1, 0, 0><<<AGG_BLOCKS, 256>>>(p_y, p_ef, p_cnt_e, p_csr_e, p_se, nullptr,
                                        0, N_EDGES);
    k_agg<0, 0, 1><<<AGG_BLOCKS, 256>>>(p_ef, out, p_cnt_n, p_csr_n, p_dinv, b2,
                                        0, N_NODES);
}